// round 10
// baseline (speedup 1.0000x reference)
#include <cuda_runtime.h>
#include <cstdint>

// Problem constants
#define T_LEN 512
#define BATCH 64
#define HID   256
#define G4    1024           // 4*HID
#define NBLK  64             // persistent CTAs for recurrence

// ---------------- device scratch (no allocations allowed) ----------------
__device__ float g_xg[(size_t)T_LEN * G4 * BATCH];   // [T][4H][B]  134 MB
__device__ float g_y0[(size_t)T_LEN * HID * BATCH];  // [T][H][B]   33.5 MB (layer0 out)
__device__ float g_h [2 * BATCH * HID];              // double-buffered h carry [h][b]
__device__ float g_masks[6 * BATCH * HID];           // [layer][{out,h,c}][b*256+h]
__device__ unsigned g_barcnt;                        // zero-init
__device__ unsigned g_bargen;                        // zero-init, monotonic across replays

// ---------------- threefry2x32-20 (JAX-exact) ----------------
__device__ __forceinline__ uint32_t rotl32(uint32_t x, int r) {
    return (x << r) | (x >> (32 - r));
}

__device__ __forceinline__ void threefry2x32(uint32_t k0, uint32_t k1,
                                             uint32_t c0, uint32_t c1,
                                             uint32_t& o0, uint32_t& o1) {
    uint32_t ks0 = k0, ks1 = k1, ks2 = k0 ^ k1 ^ 0x1BD11BDAu;
    uint32_t x0 = c0 + ks0, x1 = c1 + ks1;
    const int ra0 = 13, ra1 = 15, ra2 = 26, ra3 = 6;
    const int rb0 = 17, rb1 = 29, rb2 = 16, rb3 = 24;
#define TF_R(r) { x0 += x1; x1 = rotl32(x1, r); x1 ^= x0; }
    TF_R(ra0) TF_R(ra1) TF_R(ra2) TF_R(ra3)  x0 += ks1; x1 += ks2 + 1u;
    TF_R(rb0) TF_R(rb1) TF_R(rb2) TF_R(rb3)  x0 += ks2; x1 += ks0 + 2u;
    TF_R(ra0) TF_R(ra1) TF_R(ra2) TF_R(ra3)  x0 += ks0; x1 += ks1 + 3u;
    TF_R(rb0) TF_R(rb1) TF_R(rb2) TF_R(rb3)  x0 += ks1; x1 += ks2 + 4u;
    TF_R(ra0) TF_R(ra1) TF_R(ra2) TF_R(ra3)  x0 += ks2; x1 += ks0 + 5u;
#undef TF_R
    o0 = x0; o1 = x1;
}

// masks: partitionable-threefry semantics.
// root = (0,42). layer_key[L] = TF(root,(0,L)). sub_key[j] = TF(layer_key,(0,j)).
// bits(i) = lane0 ^ lane1 of TF(sub_key,(0,i)); u = f32(bits>>9|0x3f800000)-1; keep if u<0.75.
__global__ void mask_kernel() {
    int idx = blockIdx.x * blockDim.x + threadIdx.x;     // < 6*16384
    int mid = idx >> 14;                                 // 0..5
    int i   = idx & 16383;
    int layer = mid / 3, j = mid % 3;
    uint32_t a0, a1, b0, b1, r0, r1;
    threefry2x32(0u, 42u, 0u, (uint32_t)layer, a0, a1);  // layer key
    threefry2x32(a0, a1, 0u, (uint32_t)j, b0, b1);       // sub key
    threefry2x32(b0, b1, 0u, (uint32_t)i, r0, r1);       // random bits
    uint32_t bits = r0 ^ r1;
    float u = __uint_as_float((bits >> 9) | 0x3f800000u) - 1.0f;
    g_masks[idx] = (u < 0.75f) ? (1.0f / 0.75f) : 0.0f;
}

// ---------------- xg GEMM: xg[t][n][b] = sum_k A[t,b,k]*W[n,k] + (bih[n]+bhh[n]) ----
// a_mode 0: A = x layout [B][T][K]  (addr b*131072 + t*256 + k)
// a_mode 1: A = g_y0 layout [T][K][B] (addr t*16384 + k*64 + b)
__global__ __launch_bounds__(256) void gemm_xg(const float* __restrict__ A_ext, int a_mode,
                                               const float* __restrict__ W,
                                               const float* __restrict__ bih,
                                               const float* __restrict__ bhh) {
    const int t  = blockIdx.y;
    const int n0 = blockIdx.x * 64;
    __shared__ float As[16][64];
    __shared__ float Bs[16][64];
    const int tid = threadIdx.x;
    const int tx = tid & 15, ty = tid >> 4;
    float acc[4][4];
#pragma unroll
    for (int i = 0; i < 4; i++)
#pragma unroll
        for (int j = 0; j < 4; j++) acc[i][j] = 0.0f;

    for (int k0 = 0; k0 < 256; k0 += 16) {
        if (a_mode == 0) {
            int b  = tid >> 2;
            int kk = (tid & 3) * 4;
            float4 v = *(const float4*)&A_ext[(size_t)b * 131072 + (size_t)t * 256 + k0 + kk];
            As[kk + 0][b] = v.x; As[kk + 1][b] = v.y; As[kk + 2][b] = v.z; As[kk + 3][b] = v.w;
        } else {
            int kk = tid >> 4;
            int b4 = (tid & 15) * 4;
            float4 v = *(const float4*)&g_y0[(size_t)t * 16384 + (size_t)(k0 + kk) * 64 + b4];
            *(float4*)&As[kk][b4] = v;
        }
        {
            int n  = tid >> 2;
            int kk = (tid & 3) * 4;
            float4 v = *(const float4*)&W[(size_t)(n0 + n) * 256 + k0 + kk];
            Bs[kk + 0][n] = v.x; Bs[kk + 1][n] = v.y; Bs[kk + 2][n] = v.z; Bs[kk + 3][n] = v.w;
        }
        __syncthreads();
#pragma unroll
        for (int kk = 0; kk < 16; kk++) {
            float4 av = *(const float4*)&As[kk][ty * 4];
            float4 bv = *(const float4*)&Bs[kk][tx * 4];
            acc[0][0] += av.x * bv.x; acc[0][1] += av.x * bv.y; acc[0][2] += av.x * bv.z; acc[0][3] += av.x * bv.w;
            acc[1][0] += av.y * bv.x; acc[1][1] += av.y * bv.y; acc[1][2] += av.y * bv.z; acc[1][3] += av.y * bv.w;
            acc[2][0] += av.z * bv.x; acc[2][1] += av.z * bv.y; acc[2][2] += av.z * bv.z; acc[2][3] += av.z * bv.w;
            acc[3][0] += av.w * bv.x; acc[3][1] += av.w * bv.y; acc[3][2] += av.w * bv.z; acc[3][3] += av.w * bv.w;
        }
        __syncthreads();
    }
    float bb[4];
#pragma unroll
    for (int j = 0; j < 4; j++) bb[j] = bih[n0 + tx * 4 + j] + bhh[n0 + tx * 4 + j];
#pragma unroll
    for (int j = 0; j < 4; j++) {
        float4 o;
        o.x = acc[0][j] + bb[j]; o.y = acc[1][j] + bb[j];
        o.z = acc[2][j] + bb[j]; o.w = acc[3][j] + bb[j];
        *(float4*)&g_xg[(size_t)t * 65536 + (size_t)(n0 + tx * 4 + j) * 64 + ty * 4] = o;
    }
}

// ---------------- persistent recurrence ----------------
__device__ __forceinline__ void grid_bar(unsigned& target) {
    __threadfence();
    __syncthreads();
    if (threadIdx.x == 0) {
        target += 1;
        unsigned old = atomicAdd(&g_barcnt, 1);
        if (old == NBLK - 1) {
            atomicExch(&g_barcnt, 0);
            __threadfence();
            atomicAdd(&g_bargen, 1);
        } else {
            while ((int)(*(volatile unsigned*)&g_bargen - target) < 0) { }
        }
    }
    __syncthreads();
}

// One thread = one (b, h) cell. CTA owns 4 h-indices (16 W_hh rows, kept in smem
// transposed [k][hl][gate] so the per-k weight read is one broadcast LDS128).
// h carry double-buffered in g_h ([h][b] layout, st.cg/ld.cg), c carry in a register.
__global__ __launch_bounds__(256) void lstm_recur(const float* __restrict__ Whh,
                                                  int layer, int out_mode,
                                                  float* __restrict__ out_ext) {
    extern __shared__ float sm[];
    float* wsm = sm;            // 256*16 floats (16 KB)
    float* hsm = sm + 4096;     // 256*64 floats (64 KB), layout [k][b]

    const int tid = threadIdx.x;
    const int hl  = tid >> 6;          // 0..3
    const int b   = tid & 63;          // 0..63
    const int hg  = blockIdx.x * 4 + hl;

    // load W_hh rows into smem: wsm[k*16 + hl*4 + g] = Whh[(g*256+hg)*256 + k]
    {
        int r   = tid >> 4;            // 0..15
        int g2  = r >> 2, hl2 = r & 3;
        int hg2 = blockIdx.x * 4 + hl2;
        int kk0 = (tid & 15) * 16;
        const float* src = &Whh[(size_t)(g2 * 256 + hg2) * 256 + kk0];
#pragma unroll
        for (int j = 0; j < 16; j += 4) {
            float4 v = *(const float4*)&src[j];
            wsm[(kk0 + j + 0) * 16 + hl2 * 4 + g2] = v.x;
            wsm[(kk0 + j + 1) * 16 + hl2 * 4 + g2] = v.y;
            wsm[(kk0 + j + 2) * 16 + hl2 * 4 + g2] = v.z;
            wsm[(kk0 + j + 3) * 16 + hl2 * 4 + g2] = v.w;
        }
    }

    const float* mbase = g_masks + (size_t)layer * 3 * 16384;
    const float mo = mbase[b * 256 + hg];
    const float mh = mbase[16384 + b * 256 + hg];
    const float mc = mbase[32768 + b * 256 + hg];

    unsigned bar_target = 0;
    if (tid == 0) bar_target = *(volatile unsigned*)&g_bargen;

    __stcg(&g_h[hg * 64 + b], 0.0f);   // h0 = 0 (buffer 0)
    float cm = 0.0f;                   // masked c carry
    grid_bar(bar_target);

    const float4* w4 = (const float4*)wsm;

    for (int t = 0; t < T_LEN; t++) {
        const float* hsrc = g_h + (t & 1) * 16384;
        float*       hdst = g_h + ((t + 1) & 1) * 16384;

        // stage h_prev into smem (coherent L2 read)
#pragma unroll
        for (int i = 0; i < 16; i++) {
            int idx = i * 256 + tid;
            float4 v = __ldcg((const float4*)hsrc + idx);
            ((float4*)hsm)[idx] = v;
        }
        __syncthreads();

        size_t xb = (size_t)t * 65536 + (size_t)hg * 64 + b;
        float a0 = g_xg[xb];
        float a1 = g_xg[xb + 16384];
        float a2 = g_xg[xb + 32768];
        float a3 = g_xg[xb + 49152];

#pragma unroll 8
        for (int k = 0; k < 256; k++) {
            float  hv = hsm[k * 64 + b];   // conflict-free across lanes
            float4 w  = w4[k * 4 + hl];    // warp-broadcast
            a0 += hv * w.x;
            a1 += hv * w.y;
            a2 += hv * w.z;
            a3 += hv * w.w;
        }

        float ig = 1.0f / (1.0f + __expf(-a0));
        float fg = 1.0f / (1.0f + __expf(-a1));
        float gv = tanhf(a2);
        float og = 1.0f / (1.0f + __expf(-a3));
        float c  = fg * cm + ig * gv;
        float h  = og * tanhf(c);

        if (out_mode == 0) {
            g_y0[(size_t)t * 16384 + (size_t)hg * 64 + b] = h * mo;   // [T][H][B]
        } else {
            out_ext[(size_t)b * 131072 + (size_t)t * 256 + hg] = h * mo;  // [B][T][H]
        }
        __stcg(&hdst[hg * 64 + b], h * mh);
        cm = c * mc;

        grid_bar(bar_target);   // includes threadfence + smem reuse protection
    }
}

// ---------------- launch ----------------
extern "C" void kernel_launch(void* const* d_in, const int* in_sizes, int n_in,
                              void* d_out, int out_size) {
    const float* x    = (const float*)d_in[0];
    const float* Wih0 = (const float*)d_in[1];
    const float* Whh0 = (const float*)d_in[2];
    const float* bih0 = (const float*)d_in[3];
    const float* bhh0 = (const float*)d_in[4];
    const float* Wih1 = (const float*)d_in[5];
    const float* Whh1 = (const float*)d_in[6];
    const float* bih1 = (const float*)d_in[7];
    const float* bhh1 = (const float*)d_in[8];
    float* out = (float*)d_out;

    cudaFuncSetAttribute(lstm_recur, cudaFuncAttributeMaxDynamicSharedMemorySize, 81920);

    mask_kernel<<<96, 1024>>>();

    dim3 gg(16, T_LEN);
    gemm_xg<<<gg, 256>>>(x, 0, Wih0, bih0, bhh0);
    lstm_recur<<<NBLK, 256, 81920>>>(Whh0, 0, 0, nullptr);
    gemm_xg<<<gg, 256>>>(nullptr, 1, Wih1, bih1, bhh1);
    lstm_recur<<<NBLK, 256, 81920>>>(Whh1, 1, 1, out);
}

// round 13
// speedup vs baseline: 1.4022x; 1.4022x over previous
#include <cuda_runtime.h>
#include <cstdint>

// Problem constants
#define T_LEN 512
#define BATCH 64
#define HID   256
#define G4    1024           // 4*HID
#define NGRP  2              // batch groups (independent barriers)
#define CTA_PER_GRP 64       // CTAs per group (4 h each)

// ---------------- device scratch (no allocations allowed) ----------------
__device__ float g_xg[(size_t)T_LEN * G4 * BATCH];   // [T][4H][B]  134 MB
__device__ float g_y0[(size_t)T_LEN * HID * BATCH];  // [T][H][B]   33.5 MB (layer0 out)
__device__ float g_h [2 * BATCH * HID];              // double-buffered h carry [h][b]
__device__ float g_masks[6 * BATCH * HID];           // [layer][{out,h,c}][b*256+h]
__device__ unsigned g_barcnt2[NGRP];                 // zero-init
__device__ unsigned g_bargen2[NGRP];                 // zero-init, monotonic across replays

// ---------------- packed f32x2 helpers (Blackwell FFMA2) ----------------
typedef unsigned long long ull;

__device__ __forceinline__ ull ffma2(ull a, ull b, ull c) {
    ull d;
    asm("fma.rn.f32x2 %0, %1, %2, %3;" : "=l"(d) : "l"(a), "l"(b), "l"(c));
    return d;
}
__device__ __forceinline__ ull addf2(ull a, ull b) {
    ull d;
    asm("add.rn.f32x2 %0, %1, %2;" : "=l"(d) : "l"(a), "l"(b));
    return d;
}
__device__ __forceinline__ ull dup2(float x) {
    ull d;
    unsigned u = __float_as_uint(x);
    asm("mov.b64 %0, {%1, %1};" : "=l"(d) : "r"(u));
    return d;
}
__device__ __forceinline__ ull pack2(float lo, float hi) {
    ull d;
    asm("mov.b64 %0, {%1, %2};" : "=l"(d) : "f"(lo), "f"(hi));
    return d;
}
__device__ __forceinline__ float2 unpack2(ull v) {
    float lo, hi;
    asm("mov.b64 {%0, %1}, %2;" : "=f"(lo), "=f"(hi) : "l"(v));
    return make_float2(lo, hi);
}

// ---------------- threefry2x32-20 (JAX-exact) ----------------
__device__ __forceinline__ uint32_t rotl32(uint32_t x, int r) {
    return (x << r) | (x >> (32 - r));
}

__device__ __forceinline__ void threefry2x32(uint32_t k0, uint32_t k1,
                                             uint32_t c0, uint32_t c1,
                                             uint32_t& o0, uint32_t& o1) {
    uint32_t ks0 = k0, ks1 = k1, ks2 = k0 ^ k1 ^ 0x1BD11BDAu;
    uint32_t x0 = c0 + ks0, x1 = c1 + ks1;
    const int ra0 = 13, ra1 = 15, ra2 = 26, ra3 = 6;
    const int rb0 = 17, rb1 = 29, rb2 = 16, rb3 = 24;
#define TF_R(r) { x0 += x1; x1 = rotl32(x1, r); x1 ^= x0; }
    TF_R(ra0) TF_R(ra1) TF_R(ra2) TF_R(ra3)  x0 += ks1; x1 += ks2 + 1u;
    TF_R(rb0) TF_R(rb1) TF_R(rb2) TF_R(rb3)  x0 += ks2; x1 += ks0 + 2u;
    TF_R(ra0) TF_R(ra1) TF_R(ra2) TF_R(ra3)  x0 += ks0; x1 += ks1 + 3u;
    TF_R(rb0) TF_R(rb1) TF_R(rb2) TF_R(rb3)  x0 += ks1; x1 += ks2 + 4u;
    TF_R(ra0) TF_R(ra1) TF_R(ra2) TF_R(ra3)  x0 += ks2; x1 += ks0 + 5u;
#undef TF_R
    o0 = x0; o1 = x1;
}

// masks: partitionable-threefry semantics (verified correct in round 10 bench).
__global__ void mask_kernel() {
    int idx = blockIdx.x * blockDim.x + threadIdx.x;     // < 6*16384
    int mid = idx >> 14;                                 // 0..5
    int i   = idx & 16383;
    int layer = mid / 3, j = mid % 3;
    uint32_t a0, a1, b0, b1, r0, r1;
    threefry2x32(0u, 42u, 0u, (uint32_t)layer, a0, a1);  // layer key
    threefry2x32(a0, a1, 0u, (uint32_t)j, b0, b1);       // sub key
    threefry2x32(b0, b1, 0u, (uint32_t)i, r0, r1);       // random bits
    uint32_t bits = r0 ^ r1;
    float u = __uint_as_float((bits >> 9) | 0x3f800000u) - 1.0f;
    g_masks[idx] = (u < 0.75f) ? (1.0f / 0.75f) : 0.0f;
}

// ---------------- xg GEMM: xg[t][n][b] = sum_k A[t,b,k]*W[n,k] + (bih[n]+bhh[n]) ----
// a_mode 0: A = x layout [B][T][K]  (addr b*131072 + t*256 + k)
// a_mode 1: A = g_y0 layout [T][K][B] (addr t*16384 + k*64 + b)
__global__ __launch_bounds__(256) void gemm_xg(const float* __restrict__ A_ext, int a_mode,
                                               const float* __restrict__ W,
                                               const float* __restrict__ bih,
                                               const float* __restrict__ bhh) {
    const int t  = blockIdx.y;
    const int n0 = blockIdx.x * 64;
    __shared__ float As[16][64];
    __shared__ float Bs[16][64];
    const int tid = threadIdx.x;
    const int tx = tid & 15, ty = tid >> 4;
    float acc[4][4];
#pragma unroll
    for (int i = 0; i < 4; i++)
#pragma unroll
        for (int j = 0; j < 4; j++) acc[i][j] = 0.0f;

    for (int k0 = 0; k0 < 256; k0 += 16) {
        if (a_mode == 0) {
            int b  = tid >> 2;
            int kk = (tid & 3) * 4;
            float4 v = *(const float4*)&A_ext[(size_t)b * 131072 + (size_t)t * 256 + k0 + kk];
            As[kk + 0][b] = v.x; As[kk + 1][b] = v.y; As[kk + 2][b] = v.z; As[kk + 3][b] = v.w;
        } else {
            int kk = tid >> 4;
            int b4 = (tid & 15) * 4;
            float4 v = *(const float4*)&g_y0[(size_t)t * 16384 + (size_t)(k0 + kk) * 64 + b4];
            *(float4*)&As[kk][b4] = v;
        }
        {
            int n  = tid >> 2;
            int kk = (tid & 3) * 4;
            float4 v = *(const float4*)&W[(size_t)(n0 + n) * 256 + k0 + kk];
            Bs[kk + 0][n] = v.x; Bs[kk + 1][n] = v.y; Bs[kk + 2][n] = v.z; Bs[kk + 3][n] = v.w;
        }
        __syncthreads();
#pragma unroll
        for (int kk = 0; kk < 16; kk++) {
            float4 av = *(const float4*)&As[kk][ty * 4];
            float4 bv = *(const float4*)&Bs[kk][tx * 4];
            acc[0][0] += av.x * bv.x; acc[0][1] += av.x * bv.y; acc[0][2] += av.x * bv.z; acc[0][3] += av.x * bv.w;
            acc[1][0] += av.y * bv.x; acc[1][1] += av.y * bv.y; acc[1][2] += av.y * bv.z; acc[1][3] += av.y * bv.w;
            acc[2][0] += av.z * bv.x; acc[2][1] += av.z * bv.y; acc[2][2] += av.z * bv.z; acc[2][3] += av.z * bv.w;
            acc[3][0] += av.w * bv.x; acc[3][1] += av.w * bv.y; acc[3][2] += av.w * bv.z; acc[3][3] += av.w * bv.w;
        }
        __syncthreads();
    }
    float bb[4];
#pragma unroll
    for (int j = 0; j < 4; j++) bb[j] = bih[n0 + tx * 4 + j] + bhh[n0 + tx * 4 + j];
#pragma unroll
    for (int j = 0; j < 4; j++) {
        float4 o;
        o.x = acc[0][j] + bb[j]; o.y = acc[1][j] + bb[j];
        o.z = acc[2][j] + bb[j]; o.w = acc[3][j] + bb[j];
        *(float4*)&g_xg[(size_t)t * 65536 + (size_t)(n0 + tx * 4 + j) * 64 + ty * 4] = o;
    }
}

// ---------------- persistent recurrence (per batch-group barrier) ----------------
__device__ __forceinline__ void grid_bar(int grp, unsigned& target) {
    __threadfence();
    __syncthreads();
    if (threadIdx.x == 0) {
        target += 1;
        unsigned old = atomicAdd(&g_barcnt2[grp], 1);
        if (old == CTA_PER_GRP - 1) {
            atomicExch(&g_barcnt2[grp], 0);
            __threadfence();
            atomicAdd(&g_bargen2[grp], 1);
        } else {
            while ((int)(*(volatile unsigned*)&g_bargen2[grp] - target) < 0) { }
        }
    }
    __syncthreads();
}

// grid = 128 CTAs (2 batch groups x 64 CTAs), 128 threads.
// CTA (grp, cid) owns hg = cid*4 + hl (hl 0..3) for batches b = grp*32 + bl (bl 0..31).
// One thread = one (hg, b) cell; 4 gate dot-products as packed f32x2 FFMA2.
// W_hh smem layout [k][hl][gate] (float4 -> two packed pairs per LDS128).
// h carry double-buffered in g_h ([h][b], st.cg/ld.cg), c carry in a register.
__global__ __launch_bounds__(128) void lstm_recur(const float* __restrict__ Whh,
                                                  int layer, int out_mode,
                                                  float* __restrict__ out_ext) {
    extern __shared__ float sm[];
    float* wsm = sm;            // 256*16 floats (16 KB): [k][hl][gate]
    float* hsm = sm + 4096;     // 256*32 floats (32 KB): [k][bl]

    const int tid = threadIdx.x;
    const int hl  = tid >> 5;              // 0..3
    const int bl  = tid & 31;              // 0..31
    const int cid = blockIdx.x & 63;
    const int grp = blockIdx.x >> 6;
    const int hg  = cid * 4 + hl;
    const int b   = grp * 32 + bl;

    // load 16 W_hh rows into smem transposed: wsm[k*16 + hl*4 + g]
    {
        int r   = tid >> 3;                // 0..15
        int g2  = r >> 2, hl2 = r & 3;
        int hg2 = cid * 4 + hl2;
        int kk0 = (tid & 7) * 32;
        const float* src = &Whh[(size_t)(g2 * 256 + hg2) * 256 + kk0];
#pragma unroll
        for (int j = 0; j < 32; j += 4) {
            float4 v = *(const float4*)&src[j];
            wsm[(kk0 + j + 0) * 16 + hl2 * 4 + g2] = v.x;
            wsm[(kk0 + j + 1) * 16 + hl2 * 4 + g2] = v.y;
            wsm[(kk0 + j + 2) * 16 + hl2 * 4 + g2] = v.z;
            wsm[(kk0 + j + 3) * 16 + hl2 * 4 + g2] = v.w;
        }
    }

    const float* mbase = g_masks + (size_t)layer * 3 * 16384;
    const float mo = mbase[b * 256 + hg];
    const float mh = mbase[16384 + b * 256 + hg];
    const float mc = mbase[32768 + b * 256 + hg];

    unsigned bar_target = 0;
    if (tid == 0) bar_target = *(volatile unsigned*)&g_bargen2[grp];

    __stcg(&g_h[hg * 64 + b], 0.0f);   // h0 = 0 (buffer 0); grid covers all cells once
    float cm = 0.0f;                   // masked c carry
    grid_bar(grp, bar_target);

    for (int t = 0; t < T_LEN; t++) {
        const float* hsrc = g_h + (t & 1) * 16384;
        float*       hdst = g_h + ((t + 1) & 1) * 16384;

        // prefetch this step's xg early (independent of the h exchange)
        size_t xb = (size_t)t * 65536 + (size_t)hg * 64 + b;
        float a_i = g_xg[xb];
        float a_f = g_xg[xb + 16384];
        float a_g = g_xg[xb + 32768];
        float a_o = g_xg[xb + 49152];

        // stage this group's h columns into smem: hsm[k*32 + bl]
#pragma unroll
        for (int i = 0; i < 16; i++) {
            int f4i = i * 128 + tid;               // 0..2047
            int k   = f4i >> 3;
            int rem = f4i & 7;
            float4 v = __ldcg((const float4*)hsrc + k * 16 + grp * 8 + rem);
            ((float4*)hsm)[f4i] = v;
        }
        __syncthreads();

        ull acc01a = pack2(a_i, a_f);
        ull acc23a = pack2(a_g, a_o);
        ull acc01b = pack2(0.0f, 0.0f);
        ull acc23b = pack2(0.0f, 0.0f);

#pragma unroll 4
        for (int k = 0; k < 256; k += 2) {
            float hv0 = hsm[k * 32 + bl];              // conflict-free across lanes
            float hv1 = hsm[(k + 1) * 32 + bl];
            ull h0 = dup2(hv0);
            ull h1 = dup2(hv1);
            ulonglong2 w0 = *(const ulonglong2*)&wsm[k * 16 + hl * 4];        // broadcast LDS128
            ulonglong2 w1 = *(const ulonglong2*)&wsm[(k + 1) * 16 + hl * 4];
            acc01a = ffma2(h0, w0.x, acc01a);
            acc23a = ffma2(h0, w0.y, acc23a);
            acc01b = ffma2(h1, w1.x, acc01b);
            acc23b = ffma2(h1, w1.y, acc23b);
        }

        float2 s01 = unpack2(addf2(acc01a, acc01b));
        float2 s23 = unpack2(addf2(acc23a, acc23b));

        float ig = 1.0f / (1.0f + __expf(-s01.x));
        float fg = 1.0f / (1.0f + __expf(-s01.y));
        float gv = tanhf(s23.x);
        float og = 1.0f / (1.0f + __expf(-s23.y));
        float c  = fg * cm + ig * gv;
        float h  = og * tanhf(c);

        if (out_mode == 0) {
            g_y0[(size_t)t * 16384 + (size_t)hg * 64 + b] = h * mo;        // [T][H][B]
        } else {
            out_ext[(size_t)b * 131072 + (size_t)t * 256 + hg] = h * mo;   // [B][T][H]
        }
        __stcg(&hdst[hg * 64 + b], h * mh);
        cm = c * mc;

        grid_bar(grp, bar_target);   // release h writes + protect hsm reuse
    }
}

// ---------------- launch ----------------
extern "C" void kernel_launch(void* const* d_in, const int* in_sizes, int n_in,
                              void* d_out, int out_size) {
    const float* x    = (const float*)d_in[0];
    const float* Wih0 = (const float*)d_in[1];
    const float* Whh0 = (const float*)d_in[2];
    const float* bih0 = (const float*)d_in[3];
    const float* bhh0 = (const float*)d_in[4];
    const float* Wih1 = (const float*)d_in[5];
    const float* Whh1 = (const float*)d_in[6];
    const float* bih1 = (const float*)d_in[7];
    const float* bhh1 = (const float*)d_in[8];
    float* out = (float*)d_out;

    cudaFuncSetAttribute(lstm_recur, cudaFuncAttributeMaxDynamicSharedMemorySize, 49152);

    mask_kernel<<<96, 1024>>>();

    dim3 gg(16, T_LEN);
    gemm_xg<<<gg, 256>>>(x, 0, Wih0, bih0, bhh0);
    lstm_recur<<<NGRP * CTA_PER_GRP, 128, 49152>>>(Whh0, 0, 0, nullptr);
    gemm_xg<<<gg, 256>>>(nullptr, 1, Wih1, bih1, bhh1);
    lstm_recur<<<NGRP * CTA_PER_GRP, 128, 49152>>>(Whh1, 1, 1, out);
}